// round 2
// baseline (speedup 1.0000x reference)
#include <cuda_runtime.h>
#include <math.h>

// Problem constants
#define B_    32
#define S_    512
#define DIN_  512
#define DH_   1024
#define DOUT_ 512
#define NG_   4096   // 4 * DH_

// -------- scratch (device globals; no allocation allowed) --------
__device__ float g_gatesx[S_ * B_ * NG_];   // [t][b][4096]  (256 MB)
__device__ float g_hs[S_ * B_ * DH_];       // [t][b][1024]  (64 MB)
__device__ float g_h0[B_ * DH_];
__device__ float g_h1[B_ * DH_];
__device__ float g_c [B_ * DH_];

// ----------------------------------------------------------------
// init: zero h0 and c
// ----------------------------------------------------------------
__global__ void init_state_kernel() {
    int i = blockIdx.x * blockDim.x + threadIdx.x;
    if (i < B_ * DH_) {
        g_h0[i] = 0.0f;
        g_c[i]  = 0.0f;
    }
}

// ----------------------------------------------------------------
// Phase 1: gates_x = x @ Wx(4 gates) + bias
//   C[m, n],  m = t*32 + b  (so rows of g_gatesx are [t][b][:]),
//   A row = x[(b*S + t)*512 ...], B col n: gate = n>>10, j = n&1023,
//   W element = W_gate[k*1024 + j]  (k in 0..511 = x part)
// Tiled 64x64x16, 256 threads, 4x4 microtile.
// ----------------------------------------------------------------
__global__ __launch_bounds__(256)
void gemm_gatesx_kernel(const float* __restrict__ x,
                        const float* __restrict__ Wf, const float* __restrict__ bf,
                        const float* __restrict__ Wi, const float* __restrict__ bi,
                        const float* __restrict__ Wg, const float* __restrict__ bg,
                        const float* __restrict__ Wo, const float* __restrict__ bo)
{
    const int n0 = blockIdx.x * 64;          // 0..4095, tile within one gate (64 | 1024)
    const int m0 = blockIdx.y * 64;          // 0..16383

    const int gate  = n0 >> 10;
    const int jbase = n0 & 1023;
    const float* W    = (gate == 0) ? Wf : (gate == 1) ? Wi : (gate == 2) ? Wg : Wo;
    const float* bias = (gate == 0) ? bf : (gate == 1) ? bi : (gate == 2) ? bg : bo;

    __shared__ float As[16][65];   // [k][m], padded
    __shared__ float Bs[16][64];   // [k][n]

    const int tx = threadIdx.x;    // 0..15
    const int ty = threadIdx.y;    // 0..15
    const int tid = ty * 16 + tx;

    // A-load mapping: one float4 per thread
    const int lm  = tid >> 2;          // 0..63
    const int lk4 = (tid & 3) * 4;     // 0,4,8,12
    const int m_a = m0 + lm;
    const int b_a = m_a & 31;
    const int t_a = m_a >> 5;
    const float* xrow = x + ((size_t)b_a * S_ + t_a) * DIN_;

    // B-load mapping: one float4 per thread
    const int lkb = tid >> 4;          // 0..15
    const int ln4 = (tid & 15) * 4;    // 0..60

    float acc[4][4];
#pragma unroll
    for (int i = 0; i < 4; i++)
#pragma unroll
        for (int j = 0; j < 4; j++) acc[i][j] = 0.0f;

    for (int k0 = 0; k0 < DIN_; k0 += 16) {
        __syncthreads();
        // A tile (transposed into As[k][m])
        float4 av = *reinterpret_cast<const float4*>(xrow + k0 + lk4);
        As[lk4 + 0][lm] = av.x;
        As[lk4 + 1][lm] = av.y;
        As[lk4 + 2][lm] = av.z;
        As[lk4 + 3][lm] = av.w;
        // B tile
        *reinterpret_cast<float4*>(&Bs[lkb][ln4]) =
            *reinterpret_cast<const float4*>(W + (size_t)(k0 + lkb) * DH_ + jbase + ln4);
        __syncthreads();

#pragma unroll
        for (int kk = 0; kk < 16; kk++) {
            float a[4], bvv[4];
#pragma unroll
            for (int i = 0; i < 4; i++) a[i]   = As[kk][ty * 4 + i];
#pragma unroll
            for (int j = 0; j < 4; j++) bvv[j] = Bs[kk][tx * 4 + j];
#pragma unroll
            for (int i = 0; i < 4; i++)
#pragma unroll
                for (int j = 0; j < 4; j++)
                    acc[i][j] = fmaf(a[i], bvv[j], acc[i][j]);
        }
    }

#pragma unroll
    for (int i = 0; i < 4; i++) {
        const int row = m0 + ty * 4 + i;
#pragma unroll
        for (int j = 0; j < 4; j++) {
            const int col = n0 + tx * 4 + j;
            g_gatesx[(size_t)row * NG_ + col] = acc[i][j] + bias[jbase + tx * 4 + j];
        }
    }
}

// ----------------------------------------------------------------
// Phase 2: one recurrent step.
//   gates[b, g, j] = gates_x[t][b][g*1024+j] + sum_k h[b][k] * Wg[(512+k)*1024 + j]
//   then elementwise LSTM update. h double-buffered; c in place.
// Grid: 128 CTAs = 4 b-tiles(8 b) x 32 j-tiles(32 j). 256 threads:
//   bl = tid>>5 (warp = one batch row), jj = tid&31.
// Each warp loads one half of one gate's W chunk into smem.
// ----------------------------------------------------------------
__global__ __launch_bounds__(256)
void lstm_step_kernel(const float* __restrict__ Wf, const float* __restrict__ Wi,
                      const float* __restrict__ Wg, const float* __restrict__ Wo,
                      int t)
{
    const int jj = threadIdx.x & 31;
    const int bl = threadIdx.x >> 5;                 // 0..7 (also warp id)
    const int j0 = (blockIdx.x & 31) * 32;           // 32 j-tiles
    const int b0 = (blockIdx.x >> 5) * 8;            // 4 b-tiles
    const int b  = b0 + bl;
    const int j  = j0 + jj;

    const float* __restrict__ h_in  = (t & 1) ? g_h1 : g_h0;
    float*       __restrict__ h_out = (t & 1) ? g_h0 : g_h1;
    const float* __restrict__ gx    = g_gatesx + (size_t)t * B_ * NG_;
    float*       __restrict__ hs_t  = g_hs + (size_t)t * B_ * DH_;

    __shared__ float sh_h[8][32];        // [b-slot][k]
    __shared__ float sh_w[4][32][32];    // [gate][k][j]

    float accF = 0.f, accI = 0.f, accG = 0.f, accO = 0.f;

    // Per-warp W-load assignment: gate = bl>>1, k half = (bl&1)*16
    const int wgate = bl >> 1;
    const float* Wsel = (wgate == 0) ? Wf : (wgate == 1) ? Wi : (wgate == 2) ? Wg : Wo;
    const int kbase = (bl & 1) * 16;

    for (int k0 = 0; k0 < DH_; k0 += 32) {
        __syncthreads();
        sh_h[bl][jj] = h_in[b * DH_ + k0 + jj];
#pragma unroll
        for (int r = 0; r < 16; r++) {
            const int kk = kbase + r;
            sh_w[wgate][kk][jj] = Wsel[(size_t)(512 + k0 + kk) * DH_ + j0 + jj];
        }
        __syncthreads();

#pragma unroll
        for (int kk = 0; kk < 32; kk += 4) {
            float4 hv = *reinterpret_cast<const float4*>(&sh_h[bl][kk]);
            accF = fmaf(hv.x, sh_w[0][kk + 0][jj], accF);
            accI = fmaf(hv.x, sh_w[1][kk + 0][jj], accI);
            accG = fmaf(hv.x, sh_w[2][kk + 0][jj], accG);
            accO = fmaf(hv.x, sh_w[3][kk + 0][jj], accO);
            accF = fmaf(hv.y, sh_w[0][kk + 1][jj], accF);
            accI = fmaf(hv.y, sh_w[1][kk + 1][jj], accI);
            accG = fmaf(hv.y, sh_w[2][kk + 1][jj], accG);
            accO = fmaf(hv.y, sh_w[3][kk + 1][jj], accO);
            accF = fmaf(hv.z, sh_w[0][kk + 2][jj], accF);
            accI = fmaf(hv.z, sh_w[1][kk + 2][jj], accI);
            accG = fmaf(hv.z, sh_w[2][kk + 2][jj], accG);
            accO = fmaf(hv.z, sh_w[3][kk + 2][jj], accO);
            accF = fmaf(hv.w, sh_w[0][kk + 3][jj], accF);
            accI = fmaf(hv.w, sh_w[1][kk + 3][jj], accI);
            accG = fmaf(hv.w, sh_w[2][kk + 3][jj], accG);
            accO = fmaf(hv.w, sh_w[3][kk + 3][jj], accO);
        }
    }

    // elementwise LSTM update
    const size_t gxb = (size_t)b * NG_;
    const float zF = accF + gx[gxb + 0 * DH_ + j];
    const float zI = accI + gx[gxb + 1 * DH_ + j];
    const float zG = accG + gx[gxb + 2 * DH_ + j];
    const float zO = accO + gx[gxb + 3 * DH_ + j];

    const float fgt = 1.0f / (1.0f + expf(-zF));
    const float igt = 1.0f / (1.0f + expf(-zI));
    const float ggt = tanhf(zG);
    const float ogt = 1.0f / (1.0f + expf(-zO));

    const int ci = b * DH_ + j;
    const float cn = fgt * g_c[ci] + igt * ggt;
    g_c[ci] = cn;
    const float hn = ogt * tanhf(cn);
    h_out[ci] = hn;
    hs_t[ci]  = hn;
}

// ----------------------------------------------------------------
// Phase 3: out = hs @ W_fc + b_fc
//   A row m = t*32+b (contiguous in g_hs), K=1024, N=512.
//   Output row index = b*S + t.
// ----------------------------------------------------------------
__global__ __launch_bounds__(256)
void gemm_fc_kernel(const float* __restrict__ Wfc, const float* __restrict__ bfc,
                    float* __restrict__ out)
{
    const int n0 = blockIdx.x * 64;   // 0..511
    const int m0 = blockIdx.y * 64;   // 0..16383

    __shared__ float As[16][65];
    __shared__ float Bs[16][64];

    const int tx = threadIdx.x;
    const int ty = threadIdx.y;
    const int tid = ty * 16 + tx;

    const int lm  = tid >> 2;
    const int lk4 = (tid & 3) * 4;
    const float* arow = g_hs + (size_t)(m0 + lm) * DH_;

    const int lkb = tid >> 4;
    const int ln4 = (tid & 15) * 4;

    float acc[4][4];
#pragma unroll
    for (int i = 0; i < 4; i++)
#pragma unroll
        for (int j = 0; j < 4; j++) acc[i][j] = 0.0f;

    for (int k0 = 0; k0 < DH_; k0 += 16) {
        __syncthreads();
        float4 av = *reinterpret_cast<const float4*>(arow + k0 + lk4);
        As[lk4 + 0][lm] = av.x;
        As[lk4 + 1][lm] = av.y;
        As[lk4 + 2][lm] = av.z;
        As[lk4 + 3][lm] = av.w;
        *reinterpret_cast<float4*>(&Bs[lkb][ln4]) =
            *reinterpret_cast<const float4*>(Wfc + (size_t)(k0 + lkb) * DOUT_ + n0 + ln4);
        __syncthreads();

#pragma unroll
        for (int kk = 0; kk < 16; kk++) {
            float a[4], bvv[4];
#pragma unroll
            for (int i = 0; i < 4; i++) a[i]   = As[kk][ty * 4 + i];
#pragma unroll
            for (int j = 0; j < 4; j++) bvv[j] = Bs[kk][tx * 4 + j];
#pragma unroll
            for (int i = 0; i < 4; i++)
#pragma unroll
                for (int j = 0; j < 4; j++)
                    acc[i][j] = fmaf(a[i], bvv[j], acc[i][j]);
        }
    }

#pragma unroll
    for (int i = 0; i < 4; i++) {
        const int m = m0 + ty * 4 + i;
        const int bb = m & 31;
        const int tt = m >> 5;
        float* orow = out + ((size_t)bb * S_ + tt) * DOUT_;
#pragma unroll
        for (int j = 0; j < 4; j++) {
            const int col = n0 + tx * 4 + j;
            orow[col] = acc[i][j] + bfc[col];
        }
    }
}

// ----------------------------------------------------------------
// Launch
// ----------------------------------------------------------------
extern "C" void kernel_launch(void* const* d_in, const int* in_sizes, int n_in,
                              void* d_out, int out_size)
{
    const float* x   = (const float*)d_in[0];
    const float* Wf  = (const float*)d_in[1];
    const float* bf  = (const float*)d_in[2];
    const float* Wi  = (const float*)d_in[3];
    const float* bi  = (const float*)d_in[4];
    const float* Wg  = (const float*)d_in[5];
    const float* bg  = (const float*)d_in[6];
    const float* Wo  = (const float*)d_in[7];
    const float* bo  = (const float*)d_in[8];
    const float* Wfc = (const float*)d_in[9];
    const float* bfc = (const float*)d_in[10];
    float* out = (float*)d_out;

    // zero h0 / c
    init_state_kernel<<<(B_ * DH_ + 255) / 256, 256>>>();

    // Phase 1: input projection for all timesteps
    {
        dim3 grid(NG_ / 64, (B_ * S_) / 64);
        dim3 block(16, 16);
        gemm_gatesx_kernel<<<grid, block>>>(x, Wf, bf, Wi, bi, Wg, bg, Wo, bo);
    }

    // Phase 2: sequential recurrence
    for (int t = 0; t < S_; ++t) {
        lstm_step_kernel<<<128, 256>>>(Wf, Wi, Wg, Wo, t);
    }

    // Phase 3: output projection
    {
        dim3 grid(DOUT_ / 64, (B_ * S_) / 64);
        dim3 block(16, 16);
        gemm_fc_kernel<<<grid, block>>>(Wfc, bfc, out);
    }
}

// round 3
// speedup vs baseline: 2.2338x; 2.2338x over previous
#include <cuda_runtime.h>
#include <math.h>

// Problem constants
#define B_    32
#define S_    512
#define DIN_  512
#define DH_   1024
#define DOUT_ 512
#define NG_   4096   // 4 * DH_

#define NCTA_      128
#define HS_STRIDE  261            // 256 k + pad (stride %4 != 0 for bank safety)
#define HBUF_F     (32 * HS_STRIDE)      // 8352 floats per h buffer
#define WS_F       (DH_ * 32)            // 32768 floats of W slice
#define SMEM_F     (WS_F + 2 * HBUF_F + 256)
#define SMEM_BYTES (SMEM_F * 4)          // 198912 B

// -------- scratch (device globals; no allocation allowed) --------
__device__ float g_gatesx[S_ * B_ * NG_];   // [t][b][4096]
__device__ float g_hs[S_ * B_ * DH_];       // [t][b][1024]
__device__ float g_hb0[B_ * DH_];
__device__ float g_hb1[B_ * DH_];
__device__ unsigned g_bar;

__device__ __forceinline__ float sigf(float x) {
    return __fdividef(1.0f, 1.0f + __expf(-x));
}
__device__ __forceinline__ float tanhfast(float x) {
    return __fdividef(2.0f, 1.0f + __expf(-2.0f * x)) - 1.0f;
}

// ----------------------------------------------------------------
__global__ void init_state_kernel() {
    int i = blockIdx.x * blockDim.x + threadIdx.x;
    if (i < B_ * DH_) g_hb0[i] = 0.0f;
    if (i == 0) g_bar = 0u;
}

// ----------------------------------------------------------------
// Phase 1: gates_x = x @ Wx(4 gates) + bias   (unchanged from R1)
// ----------------------------------------------------------------
__global__ __launch_bounds__(256)
void gemm_gatesx_kernel(const float* __restrict__ x,
                        const float* __restrict__ Wf, const float* __restrict__ bf,
                        const float* __restrict__ Wi, const float* __restrict__ bi,
                        const float* __restrict__ Wg, const float* __restrict__ bg,
                        const float* __restrict__ Wo, const float* __restrict__ bo)
{
    const int n0 = blockIdx.x * 64;
    const int m0 = blockIdx.y * 64;

    const int gate  = n0 >> 10;
    const int jbase = n0 & 1023;
    const float* W    = (gate == 0) ? Wf : (gate == 1) ? Wi : (gate == 2) ? Wg : Wo;
    const float* bias = (gate == 0) ? bf : (gate == 1) ? bi : (gate == 2) ? bg : bo;

    __shared__ float As[16][65];
    __shared__ float Bs[16][64];

    const int tx = threadIdx.x;
    const int ty = threadIdx.y;
    const int tid = ty * 16 + tx;

    const int lm  = tid >> 2;
    const int lk4 = (tid & 3) * 4;
    const int m_a = m0 + lm;
    const int b_a = m_a & 31;
    const int t_a = m_a >> 5;
    const float* xrow = x + ((size_t)b_a * S_ + t_a) * DIN_;

    const int lkb = tid >> 4;
    const int ln4 = (tid & 15) * 4;

    float acc[4][4];
#pragma unroll
    for (int i = 0; i < 4; i++)
#pragma unroll
        for (int j = 0; j < 4; j++) acc[i][j] = 0.0f;

    for (int k0 = 0; k0 < DIN_; k0 += 16) {
        __syncthreads();
        float4 av = *reinterpret_cast<const float4*>(xrow + k0 + lk4);
        As[lk4 + 0][lm] = av.x;
        As[lk4 + 1][lm] = av.y;
        As[lk4 + 2][lm] = av.z;
        As[lk4 + 3][lm] = av.w;
        *reinterpret_cast<float4*>(&Bs[lkb][ln4]) =
            *reinterpret_cast<const float4*>(W + (size_t)(k0 + lkb) * DH_ + jbase + ln4);
        __syncthreads();

#pragma unroll
        for (int kk = 0; kk < 16; kk++) {
            float a[4], bvv[4];
#pragma unroll
            for (int i = 0; i < 4; i++) a[i]   = As[kk][ty * 4 + i];
#pragma unroll
            for (int j = 0; j < 4; j++) bvv[j] = Bs[kk][tx * 4 + j];
#pragma unroll
            for (int i = 0; i < 4; i++)
#pragma unroll
                for (int j = 0; j < 4; j++)
                    acc[i][j] = fmaf(a[i], bvv[j], acc[i][j]);
        }
    }

#pragma unroll
    for (int i = 0; i < 4; i++) {
        const int row = m0 + ty * 4 + i;
#pragma unroll
        for (int j = 0; j < 4; j++) {
            const int col = n0 + tx * 4 + j;
            g_gatesx[(size_t)row * NG_ + col] = acc[i][j] + bias[jbase + tx * 4 + j];
        }
    }
}

// ----------------------------------------------------------------
// Phase 2: PERSISTENT recurrence kernel.
// 128 CTAs x 256 thr, all resident. CTA owns 8 h-columns (j0..j0+7) x 4 gates.
// W slice (1024k x 32col) lives in SMEM for all 512 steps.
// Per step: h broadcast from L2 (__ldcg) into double-buffered SMEM slabs of
// 256 k; warp w computes k in [slab*256 + w*32, +32) over an 8b x 4col tile;
// cross-warp k-reduction in SMEM (aliased over h buffers); elementwise LSTM
// update; software grid barrier.
// ----------------------------------------------------------------
__global__ __launch_bounds__(256, 1)
void lstm_persist_kernel(const float* __restrict__ Wf, const float* __restrict__ Wi,
                         const float* __restrict__ Wg, const float* __restrict__ Wo)
{
    extern __shared__ float smem[];
    float* w_s   = smem;                      // [k*32 + col], col = jj*4+gate
    float* h_buf = smem + WS_F;               // 2 x HBUF_F, layout [b*261 + k_local]
    float* red_s = h_buf;                     // alias: used after slabs are done
    float* c_s   = smem + WS_F + 2 * HBUF_F;  // 256 floats

    const int tid  = threadIdx.x;
    const int lane = tid & 31;
    const int warp = tid >> 5;
    const int j0   = blockIdx.x * 8;

    // worker tile: bg (4 batch groups of 8) x cg (8 col groups of 4)
    const int bg = lane & 3;
    const int cg = lane >> 2;
    const int bbase = bg * 8;

    // ---- one-time: load W slice into SMEM ----
    for (int idx = tid; idx < WS_F; idx += 256) {
        const int k    = idx >> 5;
        const int c    = idx & 31;
        const int jj   = c >> 2;
        const int gate = c & 3;
        const float* Wsel = (gate == 0) ? Wf : (gate == 1) ? Wi : (gate == 2) ? Wg : Wo;
        w_s[idx] = Wsel[(size_t)(512 + k) * DH_ + j0 + jj];
    }
    c_s[tid] = 0.0f;
    __syncthreads();

    // elementwise mapping
    const int b_e  = tid >> 3;
    const int jj_e = tid & 7;
    const int bg_e = b_e >> 3;
    const int bb_e = b_e & 7;
    const int lane_r = jj_e * 4 + bg_e;   // reducer source lane

    volatile unsigned* barp = &g_bar;

    for (int t = 0; t < S_; ++t) {
        const float* __restrict__ h_in  = (t & 1) ? g_hb1 : g_hb0;
        float*       __restrict__ h_out = (t & 1) ? g_hb0 : g_hb1;
        const float* __restrict__ gx_t  = g_gatesx + (size_t)t * B_ * NG_;

        // prefetch gates_x epilogue values early
        float gxv[4];
#pragma unroll
        for (int g = 0; g < 4; g++)
            gxv[g] = __ldg(&gx_t[(size_t)b_e * NG_ + g * DH_ + j0 + jj_e]);

        float acc[8][4];
#pragma unroll
        for (int i = 0; i < 8; i++)
#pragma unroll
            for (int j = 0; j < 4; j++) acc[i][j] = 0.0f;

        // ---- load slab 0 ----
        {
            float* db = h_buf;  // buffer 0
#pragma unroll
            for (int p = 0; p < 8; p++) {
                const int idx = tid + p * 256;
                const int b   = idx >> 6;
                const int k4  = (idx & 63) * 4;
                const float4 v = __ldcg(reinterpret_cast<const float4*>(
                    &h_in[(size_t)b * DH_ + 0 * 256 + k4]));
                db[b * HS_STRIDE + k4 + 0] = v.x;
                db[b * HS_STRIDE + k4 + 1] = v.y;
                db[b * HS_STRIDE + k4 + 2] = v.z;
                db[b * HS_STRIDE + k4 + 3] = v.w;
            }
        }
        __syncthreads();

#pragma unroll
        for (int s = 0; s < 4; ++s) {
            // prefetch next slab into registers
            float4 pf[8];
            if (s < 3) {
#pragma unroll
                for (int p = 0; p < 8; p++) {
                    const int idx = tid + p * 256;
                    const int b   = idx >> 6;
                    const int k4  = (idx & 63) * 4;
                    pf[p] = __ldcg(reinterpret_cast<const float4*>(
                        &h_in[(size_t)b * DH_ + (s + 1) * 256 + k4]));
                }
            }

            // compute slab s: this warp handles k_local in [warp*32, warp*32+32)
            {
                const float* hb = h_buf + (s & 1) * HBUF_F + bbase * HS_STRIDE + warp * 32;
                const float* wp = w_s + (size_t)(s * 256 + warp * 32) * 32 + cg * 4;
#pragma unroll 4
                for (int kk = 0; kk < 32; ++kk) {
                    const float4 w4 = *reinterpret_cast<const float4*>(wp + kk * 32);
                    float hv[8];
#pragma unroll
                    for (int i = 0; i < 8; i++) hv[i] = hb[i * HS_STRIDE + kk];
#pragma unroll
                    for (int i = 0; i < 8; i++) {
                        acc[i][0] = fmaf(hv[i], w4.x, acc[i][0]);
                        acc[i][1] = fmaf(hv[i], w4.y, acc[i][1]);
                        acc[i][2] = fmaf(hv[i], w4.z, acc[i][2]);
                        acc[i][3] = fmaf(hv[i], w4.w, acc[i][3]);
                    }
                }
            }

            if (s < 3) {
                float* db = h_buf + ((s + 1) & 1) * HBUF_F;
#pragma unroll
                for (int p = 0; p < 8; p++) {
                    const int idx = tid + p * 256;
                    const int b   = idx >> 6;
                    const int k4  = (idx & 63) * 4;
                    db[b * HS_STRIDE + k4 + 0] = pf[p].x;
                    db[b * HS_STRIDE + k4 + 1] = pf[p].y;
                    db[b * HS_STRIDE + k4 + 2] = pf[p].z;
                    db[b * HS_STRIDE + k4 + 3] = pf[p].w;
                }
                __syncthreads();
            }
        }
        __syncthreads();   // h buffers now free -> reuse as reduction space

        // ---- cross-warp reduction: red[warp][slot][lane], slot = bb*4+cc ----
#pragma unroll
        for (int bb = 0; bb < 8; bb++)
#pragma unroll
            for (int cc = 0; cc < 4; cc++)
                red_s[warp * 1024 + (bb * 4 + cc) * 32 + lane] = acc[bb][cc];
        __syncthreads();

        // ---- final sum + LSTM elementwise (thread owns (b_e, jj_e)) ----
        float z[4];
#pragma unroll
        for (int g = 0; g < 4; g++) {
            const int slot = bb_e * 4 + g;
            float ssum = 0.0f;
#pragma unroll
            for (int w = 0; w < 8; w++)
                ssum += red_s[w * 1024 + slot * 32 + lane_r];
            z[g] = ssum + gxv[g];
        }

        const float fg = sigf(z[0]);
        const float ig = sigf(z[1]);
        const float gg = tanhfast(z[2]);
        const float og = sigf(z[3]);

        const float cn = fg * c_s[tid] + ig * gg;
        c_s[tid] = cn;
        const float hn = og * tanhfast(cn);

        const int gj = j0 + jj_e;
        h_out[(size_t)b_e * DH_ + gj] = hn;
        g_hs[(size_t)t * B_ * DH_ + (size_t)b_e * DH_ + gj] = hn;

        // ---- grid barrier ----
        __syncthreads();
        if (t < S_ - 1) {
            if (tid == 0) {
                __threadfence();
                atomicAdd((unsigned*)&g_bar, 1u);
                const unsigned target = (unsigned)(NCTA_ * (t + 1));
                while (*barp < target) { }
                __threadfence();
            }
            __syncthreads();
        }
    }
}

// ----------------------------------------------------------------
// Phase 3: out = hs @ W_fc + b_fc   (unchanged from R1)
// ----------------------------------------------------------------
__global__ __launch_bounds__(256)
void gemm_fc_kernel(const float* __restrict__ Wfc, const float* __restrict__ bfc,
                    float* __restrict__ out)
{
    const int n0 = blockIdx.x * 64;
    const int m0 = blockIdx.y * 64;

    __shared__ float As[16][65];
    __shared__ float Bs[16][64];

    const int tx = threadIdx.x;
    const int ty = threadIdx.y;
    const int tid = ty * 16 + tx;

    const int lm  = tid >> 2;
    const int lk4 = (tid & 3) * 4;
    const float* arow = g_hs + (size_t)(m0 + lm) * DH_;

    const int lkb = tid >> 4;
    const int ln4 = (tid & 15) * 4;

    float acc[4][4];
#pragma unroll
    for (int i = 0; i < 4; i++)
#pragma unroll
        for (int j = 0; j < 4; j++) acc[i][j] = 0.0f;

    for (int k0 = 0; k0 < DH_; k0 += 16) {
        __syncthreads();
        float4 av = *reinterpret_cast<const float4*>(arow + k0 + lk4);
        As[lk4 + 0][lm] = av.x;
        As[lk4 + 1][lm] = av.y;
        As[lk4 + 2][lm] = av.z;
        As[lk4 + 3][lm] = av.w;
        *reinterpret_cast<float4*>(&Bs[lkb][ln4]) =
            *reinterpret_cast<const float4*>(Wfc + (size_t)(k0 + lkb) * DOUT_ + n0 + ln4);
        __syncthreads();

#pragma unroll
        for (int kk = 0; kk < 16; kk++) {
            float a[4], bvv[4];
#pragma unroll
            for (int i = 0; i < 4; i++) a[i]   = As[kk][ty * 4 + i];
#pragma unroll
            for (int j = 0; j < 4; j++) bvv[j] = Bs[kk][tx * 4 + j];
#pragma unroll
            for (int i = 0; i < 4; i++)
#pragma unroll
                for (int j = 0; j < 4; j++)
                    acc[i][j] = fmaf(a[i], bvv[j], acc[i][j]);
        }
    }

#pragma unroll
    for (int i = 0; i < 4; i++) {
        const int m = m0 + ty * 4 + i;
        const int bb = m & 31;
        const int tt = m >> 5;
        float* orow = out + ((size_t)bb * S_ + tt) * DOUT_;
#pragma unroll
        for (int j = 0; j < 4; j++) {
            const int col = n0 + tx * 4 + j;
            orow[col] = acc[i][j] + bfc[col];
        }
    }
}

// ----------------------------------------------------------------
extern "C" void kernel_launch(void* const* d_in, const int* in_sizes, int n_in,
                              void* d_out, int out_size)
{
    const float* x   = (const float*)d_in[0];
    const float* Wf  = (const float*)d_in[1];
    const float* bf  = (const float*)d_in[2];
    const float* Wi  = (const float*)d_in[3];
    const float* bi  = (const float*)d_in[4];
    const float* Wg  = (const float*)d_in[5];
    const float* bg  = (const float*)d_in[6];
    const float* Wo  = (const float*)d_in[7];
    const float* bo  = (const float*)d_in[8];
    const float* Wfc = (const float*)d_in[9];
    const float* bfc = (const float*)d_in[10];
    float* out = (float*)d_out;

    static bool configured = false;
    if (!configured) {
        cudaFuncSetAttribute(lstm_persist_kernel,
                             cudaFuncAttributeMaxDynamicSharedMemorySize, SMEM_BYTES);
        configured = true;
    }

    init_state_kernel<<<(B_ * DH_ + 255) / 256, 256>>>();

    {
        dim3 grid(NG_ / 64, (B_ * S_) / 64);
        dim3 block(16, 16);
        gemm_gatesx_kernel<<<grid, block>>>(x, Wf, bf, Wi, bi, Wg, bg, Wo, bo);
    }

    lstm_persist_kernel<<<NCTA_, 256, SMEM_BYTES>>>(Wf, Wi, Wg, Wo);

    {
        dim3 grid(DOUT_ / 64, (B_ * S_) / 64);
        dim3 block(16, 16);
        gemm_fc_kernel<<<grid, block>>>(Wfc, bfc, out);
    }
}